// round 1
// baseline (speedup 1.0000x reference)
#include <cuda_runtime.h>
#include <cstdint>

#define EPSV 1e-5f
constexpr int BB = 32, CIN = 240, C1 = 24, HH = 56, WWD = 56, HW = 3136;
constexpr int OUP = 240;

// Scratch (9.63 MB each) — __device__ globals per allocation rules.
__device__ float g_s1[BB * C1 * HW];   // after conv1x1 + bn1
__device__ float g_s2[BB * C1 * HW];   // after dw3x3 + bn2 (== x1)

using u64 = unsigned long long;

__device__ __forceinline__ u64 pk2(float lo, float hi) {
    u64 r; asm("mov.b64 %0, {%1,%2};" : "=l"(r) : "f"(lo), "f"(hi)); return r;
}
__device__ __forceinline__ float2 up2(u64 v) {
    float2 f; asm("mov.b64 {%0,%1}, %2;" : "=f"(f.x), "=f"(f.y) : "l"(v)); return f;
}
__device__ __forceinline__ u64 fma2(u64 a, u64 b, u64 c) {
    u64 d; asm("fma.rn.f32x2 %0, %1, %2, %3;" : "=l"(d) : "l"(a), "l"(b), "l"(c)); return d;
}
__device__ __forceinline__ u64 add2(u64 a, u64 b) {
    u64 d; asm("add.rn.f32x2 %0, %1, %2;" : "=l"(d) : "l"(a), "l"(b)); return d;
}

// ---------------------------------------------------------------------------
// Kernel A: 1x1 conv (K=240 -> 24) + BN1. 4 pixels/thread, packed f32x2 FFMA.
// Weights duplicated into shared as {w,w} pairs so LDS.128 feeds 2 channels.
// ---------------------------------------------------------------------------
__global__ __launch_bounds__(128) void kA(
    const float* __restrict__ x, const float* __restrict__ w,
    const float* __restrict__ g1, const float* __restrict__ b1,
    const float* __restrict__ m1, const float* __restrict__ v1) {
    __shared__ ulonglong2 ws2[CIN * C1 / 2];   // [k][c/2], 46080 B
    __shared__ float sinv[C1], sbias[C1];
    int tid = threadIdx.x;
    u64* wsf = reinterpret_cast<u64*>(ws2);
    for (int i = tid; i < CIN * C1; i += 128) {
        int k = i / C1, c = i % C1;
        float wv = w[c * CIN + k];          // w_primary[c][k]
        wsf[k * C1 + c] = pk2(wv, wv);
    }
    if (tid < C1) {
        float iv = g1[tid] * rsqrtf(v1[tid] + EPSV);
        sinv[tid] = iv;
        sbias[tid] = b1[tid] - m1[tid] * iv;
    }
    __syncthreads();

    int g = blockIdx.x * 128 + tid;         // pixel-quad id, 25088 total
    int p0 = g * 4;
    int b = p0 / HW;
    int s = p0 - b * HW;
    const float* xp = x + (size_t)b * CIN * HW + s;

    u64 acc0[C1], acc1[C1];
#pragma unroll
    for (int c = 0; c < C1; c++) { acc0[c] = 0ull; acc1[c] = 0ull; }

#pragma unroll 4
    for (int k = 0; k < CIN; k++) {
        float4 xv = *reinterpret_cast<const float4*>(xp + (size_t)k * HW);
        u64 xa = pk2(xv.x, xv.y);
        u64 xb = pk2(xv.z, xv.w);
        const ulonglong2* wk = ws2 + k * (C1 / 2);
#pragma unroll
        for (int c2 = 0; c2 < C1 / 2; c2++) {
            ulonglong2 wv = wk[c2];
            acc0[2 * c2]     = fma2(xa, wv.x, acc0[2 * c2]);
            acc1[2 * c2]     = fma2(xb, wv.x, acc1[2 * c2]);
            acc0[2 * c2 + 1] = fma2(xa, wv.y, acc0[2 * c2 + 1]);
            acc1[2 * c2 + 1] = fma2(xb, wv.y, acc1[2 * c2 + 1]);
        }
    }
    float* op = g_s1 + (size_t)b * C1 * HW + s;
#pragma unroll
    for (int c = 0; c < C1; c++) {
        float2 a = up2(acc0[c]), bq = up2(acc1[c]);
        float iv = sinv[c], bi = sbias[c];
        float4 o = make_float4(fmaf(a.x, iv, bi), fmaf(a.y, iv, bi),
                               fmaf(bq.x, iv, bi), fmaf(bq.y, iv, bi));
        *reinterpret_cast<float4*>(op + (size_t)c * HW) = o;
    }
}

// ---------------------------------------------------------------------------
// Kernel B: depthwise 3x3 (pad 1) + BN2. 4 pixels/thread.
// Writes both g_s2 (for kernel C) and out channels [0,24).
// ---------------------------------------------------------------------------
__global__ __launch_bounds__(256) void kB(
    const float* __restrict__ wdw,
    const float* __restrict__ g2, const float* __restrict__ b2,
    const float* __restrict__ m2, const float* __restrict__ v2,
    float* __restrict__ out) {
    int idx = blockIdx.x * 256 + threadIdx.x;   // 32*24*784 quads
    int q = idx % 784;
    int c = (idx / 784) % C1;
    int b = idx / (784 * C1);
    int h = q / 14;
    int w0 = (q % 14) * 4;
    const float* p = g_s1 + ((size_t)b * C1 + c) * HW;

    float rb[3][6];
#pragma unroll
    for (int dy = 0; dy < 3; dy++) {
        int hh = h + dy - 1;
        bool hok = (hh >= 0) && (hh < HH);
#pragma unroll
        for (int jx = 0; jx < 6; jx++) {
            int ww = w0 + jx - 1;
            rb[dy][jx] = (hok && ww >= 0 && ww < WWD) ? p[hh * WWD + ww] : 0.0f;
        }
    }
    float wv[9];
#pragma unroll
    for (int t = 0; t < 9; t++) wv[t] = wdw[c * 9 + t];
    float acc[4] = {0.f, 0.f, 0.f, 0.f};
#pragma unroll
    for (int dy = 0; dy < 3; dy++)
#pragma unroll
        for (int dx = 0; dx < 3; dx++) {
            float t = wv[dy * 3 + dx];
#pragma unroll
            for (int j = 0; j < 4; j++) acc[j] = fmaf(rb[dy][dx + j], t, acc[j]);
        }
    float iv = g2[c] * rsqrtf(v2[c] + EPSV);
    float bi = b2[c] - m2[c] * iv;
    float4 o = make_float4(fmaf(acc[0], iv, bi), fmaf(acc[1], iv, bi),
                           fmaf(acc[2], iv, bi), fmaf(acc[3], iv, bi));
    size_t off = ((size_t)b * C1 + c) * HW + h * WWD + w0;
    *reinterpret_cast<float4*>(g_s2 + off) = o;
    size_t ooff = ((size_t)b * OUP + c) * HW + h * WWD + w0;
    *reinterpret_cast<float4*>(out + ooff) = o;
}

// ---------------------------------------------------------------------------
// Kernel C: adder depthwise (24 -> 216) + BN3 + ReLU into out channels [24,240).
// 4 pixels/thread as 2 packed f32x2 pairs. |a-b| = add.f32x2(a,-b) then 64-bit
// AND mask (alu pipe, overlaps fma pipe). Zero padding contributes |0 - tap|.
// ---------------------------------------------------------------------------
__global__ __launch_bounds__(128) void kC(
    const float* __restrict__ wadd,
    const float* __restrict__ g3, const float* __restrict__ b3,
    const float* __restrict__ m3, const float* __restrict__ v3,
    float* __restrict__ out) {
    int c = blockIdx.y;
    int b = blockIdx.z;
    __shared__ u64 negtap[81];          // -w_add[c][r][t], duplicated f32x2
    __shared__ float sninv[9], sbias[9];
    int tid = threadIdx.x;
    if (tid < 81) {
        float tv = wadd[c * 81 + tid];
        negtap[tid] = pk2(-tv, -tv);
    }
    if (tid < 9) {
        int ch = c * 9 + tid;
        float iv = g3[ch] * rsqrtf(v3[ch] + EPSV);
        sninv[tid] = -iv;               // y = bias - acc*inv
        sbias[tid] = b3[ch] - m3[ch] * iv;
    }
    __syncthreads();
    int q = blockIdx.x * 128 + tid;
    if (q >= 784) return;
    int h = q / 14;
    int w0 = (q % 14) * 4;
    const float* p = g_s2 + ((size_t)b * C1 + c) * HW;

    float rb[3][6];
#pragma unroll
    for (int dy = 0; dy < 3; dy++) {
        int hh = h + dy - 1;
        bool hok = (hh >= 0) && (hh < HH);
#pragma unroll
        for (int jx = 0; jx < 6; jx++) {
            int ww = w0 + jx - 1;
            rb[dy][jx] = (hok && ww >= 0 && ww < WWD) ? p[hh * WWD + ww] : 0.0f;
        }
    }
    u64 nA[9], nB[9];
#pragma unroll
    for (int dy = 0; dy < 3; dy++)
#pragma unroll
        for (int dx = 0; dx < 3; dx++) {
            nA[dy * 3 + dx] = pk2(rb[dy][dx],     rb[dy][dx + 1]);
            nB[dy * 3 + dx] = pk2(rb[dy][dx + 2], rb[dy][dx + 3]);
        }
    size_t obase = ((size_t)b * OUP + C1 + c * 9) * HW + h * WWD + w0;
#pragma unroll
    for (int r = 0; r < 9; r++) {
        u64 aA = 0ull, aB = 0ull;
#pragma unroll
        for (int t = 0; t < 9; t++) {
            u64 nt = negtap[r * 9 + t];
            u64 dA = add2(nA[t], nt) & 0x7FFFFFFF7FFFFFFFull;
            u64 dB = add2(nB[t], nt) & 0x7FFFFFFF7FFFFFFFull;
            aA = add2(aA, dA);
            aB = add2(aB, dB);
        }
        float2 fa = up2(aA), fb = up2(aB);
        float ni = sninv[r], bi = sbias[r];
        float4 o = make_float4(fmaxf(fmaf(fa.x, ni, bi), 0.f),
                               fmaxf(fmaf(fa.y, ni, bi), 0.f),
                               fmaxf(fmaf(fb.x, ni, bi), 0.f),
                               fmaxf(fmaf(fb.y, ni, bi), 0.f));
        *reinterpret_cast<float4*>(out + obase + (size_t)r * HW) = o;
    }
}

extern "C" void kernel_launch(void* const* d_in, const int* in_sizes, int n_in,
                              void* d_out, int out_size) {
    const float* x   = (const float*)d_in[0];
    const float* wp  = (const float*)d_in[1];
    const float* g1  = (const float*)d_in[2];
    const float* b1  = (const float*)d_in[3];
    const float* m1  = (const float*)d_in[4];
    const float* v1  = (const float*)d_in[5];
    const float* wdw = (const float*)d_in[6];
    const float* g2  = (const float*)d_in[7];
    const float* b2  = (const float*)d_in[8];
    const float* m2  = (const float*)d_in[9];
    const float* v2  = (const float*)d_in[10];
    const float* wa  = (const float*)d_in[11];
    const float* g3  = (const float*)d_in[12];
    const float* b3  = (const float*)d_in[13];
    const float* m3  = (const float*)d_in[14];
    const float* v3  = (const float*)d_in[15];
    float* out = (float*)d_out;

    kA<<<196, 128>>>(x, wp, g1, b1, m1, v1);                 // 25088 quads
    kB<<<2352, 256>>>(wdw, g2, b2, m2, v2, out);             // 602112 quads
    kC<<<dim3(7, 24, 32), 128>>>(wa, g3, b3, m3, v3, out);   // per (b,c) planes
}

// round 2
// speedup vs baseline: 1.1887x; 1.1887x over previous
#include <cuda_runtime.h>
#include <cstdint>

#define EPSV 1e-5f
constexpr int BB = 32, CIN = 240, C1 = 24, HH = 56, WWD = 56, HW = 3136;
constexpr int OUP = 240;

// Scratch — __device__ global per allocation rules.
__device__ float g_s1[BB * C1 * HW];   // after conv1x1 + bn1

using u64 = unsigned long long;

__device__ __forceinline__ u64 pk2(float lo, float hi) {
    u64 r; asm("mov.b64 %0, {%1,%2};" : "=l"(r) : "f"(lo), "f"(hi)); return r;
}
__device__ __forceinline__ float2 up2(u64 v) {
    float2 f; asm("mov.b64 {%0,%1}, %2;" : "=f"(f.x), "=f"(f.y) : "l"(v)); return f;
}
__device__ __forceinline__ u64 fma2(u64 a, u64 b, u64 c) {
    u64 d; asm("fma.rn.f32x2 %0, %1, %2, %3;" : "=l"(d) : "l"(a), "l"(b), "l"(c)); return d;
}
__device__ __forceinline__ u64 add2(u64 a, u64 b) {
    u64 d; asm("add.rn.f32x2 %0, %1, %2;" : "=l"(d) : "l"(a), "l"(b)); return d;
}

// ---------------------------------------------------------------------------
// Kernel A: 1x1 conv (K=240 -> 24) + BN1.
// 1 pixel/thread, channel-PAIR packed accumulators (12 x f32x2).
// Grid 392x256 = 100352 threads -> ~21 warps/SM for latency hiding.
// Per k: 1 LDG.32 (batched x8 for MLP), broadcast LDS of weight pairs, 12 fma2.
// ---------------------------------------------------------------------------
__global__ __launch_bounds__(256) void kA(
    const float* __restrict__ x, const float* __restrict__ w,
    const float* __restrict__ g1, const float* __restrict__ b1,
    const float* __restrict__ m1, const float* __restrict__ v1) {
    __shared__ u64 ws[CIN * 12];          // [k][c2] = {w[2c2][k], w[2c2+1][k]}
    __shared__ u64 bninv[12], bnbias[12];
    int tid = threadIdx.x;
    for (int i = tid; i < CIN * 12; i += 256) {
        int k = i / 12, c2 = i % 12;
        ws[i] = pk2(w[(2 * c2) * CIN + k], w[(2 * c2 + 1) * CIN + k]);
    }
    if (tid < 12) {
        int c0 = 2 * tid, c1 = 2 * tid + 1;
        float i0 = g1[c0] * rsqrtf(v1[c0] + EPSV);
        float i1 = g1[c1] * rsqrtf(v1[c1] + EPSV);
        bninv[tid] = pk2(i0, i1);
        bnbias[tid] = pk2(b1[c0] - m1[c0] * i0, b1[c1] - m1[c1] * i1);
    }
    __syncthreads();

    int p = blockIdx.x * 256 + tid;       // one pixel per thread (exact: 392*256)
    int b = p / HW;
    int s = p - b * HW;
    const float* xp = x + (size_t)b * CIN * HW + s;

    u64 acc[12];
#pragma unroll
    for (int c2 = 0; c2 < 12; c2++) acc[c2] = 0ull;

    for (int k0 = 0; k0 < CIN; k0 += 8) {
        float xv[8];
#pragma unroll
        for (int j = 0; j < 8; j++)
            xv[j] = __ldg(xp + (size_t)(k0 + j) * HW);
#pragma unroll
        for (int j = 0; j < 8; j++) {
            u64 xx = pk2(xv[j], xv[j]);
            const u64* wk = ws + (k0 + j) * 12;
#pragma unroll
            for (int c2 = 0; c2 < 12; c2++)
                acc[c2] = fma2(xx, wk[c2], acc[c2]);
        }
    }
    float* op = g_s1 + (size_t)b * C1 * HW + s;
#pragma unroll
    for (int c2 = 0; c2 < 12; c2++) {
        float2 f = up2(fma2(acc[c2], bninv[c2], bnbias[c2]));
        op[(size_t)(2 * c2) * HW] = f.x;
        op[(size_t)(2 * c2 + 1) * HW] = f.y;
    }
}

// ---------------------------------------------------------------------------
// Fused kernel BC: one block per (b,c) plane (768 blocks, 256 threads).
// Stage 1: dw3x3 + BN2 over the whole 56x56 plane -> shared tile (+ out[:, :24]).
// Stage 2: adder depthwise (9 filters) + BN3 + ReLU from shared -> out[:, 24:240].
// Eliminates the g_s2 global round-trip entirely.
// ---------------------------------------------------------------------------
__global__ __launch_bounds__(256) void kBC(
    const float* __restrict__ wdw,
    const float* __restrict__ g2, const float* __restrict__ b2,
    const float* __restrict__ m2, const float* __restrict__ v2,
    const float* __restrict__ wadd,
    const float* __restrict__ g3, const float* __restrict__ b3,
    const float* __restrict__ m3, const float* __restrict__ v3,
    float* __restrict__ out) {
    int c = blockIdx.x % C1;
    int b = blockIdx.x / C1;
    __shared__ float tile[HW];            // 12544 B dw output plane
    __shared__ u64 negtap[81];
    __shared__ float sninv[9], sbias[9];
    int tid = threadIdx.x;
    if (tid < 81) {
        float tv = wadd[c * 81 + tid];
        negtap[tid] = pk2(-tv, -tv);
    }
    if (tid < 9) {
        int ch = c * 9 + tid;
        float iv = g3[ch] * rsqrtf(v3[ch] + EPSV);
        sninv[tid] = -iv;
        sbias[tid] = b3[ch] - m3[ch] * iv;
    }
    float wv[9];
#pragma unroll
    for (int t = 0; t < 9; t++) wv[t] = __ldg(wdw + c * 9 + t);
    float iv2 = g2[c] * rsqrtf(v2[c] + EPSV);
    float bi2 = b2[c] - m2[c] * iv2;
    const float* p = g_s1 + ((size_t)b * C1 + c) * HW;
    float* outc = out + ((size_t)b * OUP + c) * HW;

    // Stage 1: dw3x3 + BN2, 4 px per iteration
    for (int q = tid; q < 784; q += 256) {
        int h = q / 14;
        int w0 = (q % 14) * 4;
        float rb[3][6];
#pragma unroll
        for (int dy = 0; dy < 3; dy++) {
            int hh = h + dy - 1;
            bool hok = (hh >= 0) && (hh < HH);
#pragma unroll
            for (int jx = 0; jx < 6; jx++) {
                int ww = w0 + jx - 1;
                rb[dy][jx] = (hok && ww >= 0 && ww < WWD) ? p[hh * WWD + ww] : 0.0f;
            }
        }
        float acc[4] = {0.f, 0.f, 0.f, 0.f};
#pragma unroll
        for (int dy = 0; dy < 3; dy++)
#pragma unroll
            for (int dx = 0; dx < 3; dx++) {
                float t = wv[dy * 3 + dx];
#pragma unroll
                for (int j = 0; j < 4; j++) acc[j] = fmaf(rb[dy][dx + j], t, acc[j]);
            }
        float4 o = make_float4(fmaf(acc[0], iv2, bi2), fmaf(acc[1], iv2, bi2),
                               fmaf(acc[2], iv2, bi2), fmaf(acc[3], iv2, bi2));
        *reinterpret_cast<float4*>(tile + h * WWD + w0) = o;
        *reinterpret_cast<float4*>(outc + h * WWD + w0) = o;
    }
    __syncthreads();

    // Stage 2: adder + BN3 + ReLU from shared tile
    float* outa = out + ((size_t)b * OUP + C1 + c * 9) * HW;
    for (int q = tid; q < 784; q += 256) {
        int h = q / 14;
        int w0 = (q % 14) * 4;
        float rb[3][6];
#pragma unroll
        for (int dy = 0; dy < 3; dy++) {
            int hh = h + dy - 1;
            bool hok = (hh >= 0) && (hh < HH);
#pragma unroll
            for (int jx = 0; jx < 6; jx++) {
                int ww = w0 + jx - 1;
                rb[dy][jx] = (hok && ww >= 0 && ww < WWD) ? tile[hh * WWD + ww] : 0.0f;
            }
        }
        u64 nA[9], nB[9];
#pragma unroll
        for (int dy = 0; dy < 3; dy++)
#pragma unroll
            for (int dx = 0; dx < 3; dx++) {
                nA[dy * 3 + dx] = pk2(rb[dy][dx],     rb[dy][dx + 1]);
                nB[dy * 3 + dx] = pk2(rb[dy][dx + 2], rb[dy][dx + 3]);
            }
        size_t obase = (size_t)h * WWD + w0;
#pragma unroll
        for (int r = 0; r < 9; r++) {
            u64 aA = 0ull, aB = 0ull;
#pragma unroll
            for (int t = 0; t < 9; t++) {
                u64 nt = negtap[r * 9 + t];
                u64 dA = add2(nA[t], nt) & 0x7FFFFFFF7FFFFFFFull;
                u64 dB = add2(nB[t], nt) & 0x7FFFFFFF7FFFFFFFull;
                aA = add2(aA, dA);
                aB = add2(aB, dB);
            }
            float2 fa = up2(aA), fb = up2(aB);
            float ni = sninv[r], bi = sbias[r];
            float4 o = make_float4(fmaxf(fmaf(fa.x, ni, bi), 0.f),
                                   fmaxf(fmaf(fa.y, ni, bi), 0.f),
                                   fmaxf(fmaf(fb.x, ni, bi), 0.f),
                                   fmaxf(fmaf(fb.y, ni, bi), 0.f));
            *reinterpret_cast<float4*>(outa + (size_t)r * HW + obase) = o;
        }
    }
}

extern "C" void kernel_launch(void* const* d_in, const int* in_sizes, int n_in,
                              void* d_out, int out_size) {
    const float* x   = (const float*)d_in[0];
    const float* wp  = (const float*)d_in[1];
    const float* g1  = (const float*)d_in[2];
    const float* b1  = (const float*)d_in[3];
    const float* m1  = (const float*)d_in[4];
    const float* v1  = (const float*)d_in[5];
    const float* wdw = (const float*)d_in[6];
    const float* g2  = (const float*)d_in[7];
    const float* b2  = (const float*)d_in[8];
    const float* m2  = (const float*)d_in[9];
    const float* v2  = (const float*)d_in[10];
    const float* wa  = (const float*)d_in[11];
    const float* g3  = (const float*)d_in[12];
    const float* b3  = (const float*)d_in[13];
    const float* m3  = (const float*)d_in[14];
    const float* v3  = (const float*)d_in[15];
    float* out = (float*)d_out;

    kA<<<392, 256>>>(x, wp, g1, b1, m1, v1);
    kBC<<<BB * C1, 256>>>(wdw, g2, b2, m2, v2, wa, g3, b3, m3, v3, out);
}